// round 6
// baseline (speedup 1.0000x reference)
#include <cuda_runtime.h>
#include <math.h>
#include <stdint.h>

#define Bsz 512
#define Tsz 512
#define Isz 64
#define Hsz 256

// Scratch: two full-sequence buffers (ping-pong between layers).
__device__ float g_seqA[Bsz * Tsz * Hsz];   // 256 MiB
__device__ float g_seqB[Bsz * Tsz * Hsz];   // 256 MiB

__device__ __forceinline__ uint32_t smem_u32(const void* p) {
    uint32_t a;
    asm("{ .reg .u64 t; cvta.to.shared.u64 t, %1; cvt.u32.u64 %0, t; }"
        : "=r"(a) : "l"(p));
    return a;
}

// ---------------------------------------------------------------------------
// Projection GEMM: C[M, Hsz] = X[M, K] @ W[Hsz, K]^T + b1 + b2
// M = B*T = 262144, K = 64 (layer 0) or 256 (layers 1,2)
// ---------------------------------------------------------------------------
#define PBM 128
#define PBN 64
#define PBK 32
#define PTM 8
#define PTN 4

__global__ __launch_bounds__(256) void proj_kernel(
    const float* __restrict__ X, const float* __restrict__ W,
    const float* __restrict__ b1, const float* __restrict__ b2,
    float* __restrict__ C, int K)
{
    __shared__ float Xs[PBK][PBM + 4];
    __shared__ float Ws[PBK][PBN + 4];

    const int tid = threadIdx.x;
    const int tx = tid & 15;
    const int ty = tid >> 4;
    const int m0 = blockIdx.x * PBM;
    const int n0 = blockIdx.y * PBN;

    float acc[PTM][PTN];
#pragma unroll
    for (int i = 0; i < PTM; i++)
#pragma unroll
        for (int j = 0; j < PTN; j++) acc[i][j] = 0.0f;

    for (int kt = 0; kt < K; kt += PBK) {
#pragma unroll
        for (int l = 0; l < 4; l++) {
            int id  = tid + 256 * l;
            int row = id >> 3;
            int kq  = (id & 7) * 4;
            float4 v = *(const float4*)&X[(m0 + row) * K + kt + kq];
            Xs[kq + 0][row] = v.x;
            Xs[kq + 1][row] = v.y;
            Xs[kq + 2][row] = v.z;
            Xs[kq + 3][row] = v.w;
        }
#pragma unroll
        for (int l = 0; l < 2; l++) {
            int id  = tid + 256 * l;
            int row = id >> 3;
            int kq  = (id & 7) * 4;
            float4 v = *(const float4*)&W[(n0 + row) * K + kt + kq];
            Ws[kq + 0][row] = v.x;
            Ws[kq + 1][row] = v.y;
            Ws[kq + 2][row] = v.z;
            Ws[kq + 3][row] = v.w;
        }
        __syncthreads();

#pragma unroll
        for (int k = 0; k < PBK; k++) {
            float a[PTM], w[PTN];
#pragma unroll
            for (int i = 0; i < PTM; i++) a[i] = Xs[k][ty * PTM + i];
#pragma unroll
            for (int j = 0; j < PTN; j++) w[j] = Ws[k][tx * PTN + j];
#pragma unroll
            for (int i = 0; i < PTM; i++)
#pragma unroll
                for (int j = 0; j < PTN; j++)
                    acc[i][j] = fmaf(a[i], w[j], acc[i][j]);
        }
        __syncthreads();
    }

#pragma unroll
    for (int j = 0; j < PTN; j++) {
        int n = n0 + tx * PTN + j;
        float bb = b1[n] + b2[n];
#pragma unroll
        for (int i = 0; i < PTM; i++) {
            C[(m0 + ty * PTM + i) * Hsz + n] = acc[i][j] + bb;
        }
    }
}

// ---------------------------------------------------------------------------
// Recurrence, W_hh register-resident, 1024 threads (32 warps -> 8/SMSP).
// 2-CTA cluster splits the output dim: CTA rank owns j in [rank*128, +128).
// Warp = 4 j-rows x 8 k-slices (lane = jl*8 + ks). Lane holds 32 W floats
// (8 float4, k = ks*32 .. +32). h stored k-interleaved: element k of row b
// lives at  b*256 + ((k>>2)&7)*32 + (k>>5)*4 + (k&3),  so each LDS.128 at
// (b, m) covers one contiguous 128B window -> 1 conflict-free wavefront.
// Partial dots reduced with a 7-shfl halving exchange; lane ks finalizes
// batch row b == ks. h exchanged with peer CTA via DSMEM. In-place on seq.
// ---------------------------------------------------------------------------
#define RMC 8            // batch rows per cluster (1 per k-slice lane)

__global__ void __launch_bounds__(1024, 1) __cluster_dims__(2, 1, 1)
rec4_kernel(const float* __restrict__ w_hh, float* __restrict__ seq)
{
    __shared__ __align__(16) float hbuf[2][RMC * Hsz];

    const int tid  = threadIdx.x;
    const int lane = tid & 31;
    const int wi   = tid >> 5;            // warp 0..31
    const int jl   = lane >> 3;           // 0..3
    const int ks   = lane & 7;            // k-slice / publish row, 0..7
    const unsigned rank = blockIdx.x & 1;
    const int jg   = (int)rank * 128 + wi * 4 + jl;   // this lane's W row
    const int b0   = (blockIdx.x >> 1) * RMC;

    // Interleaved position of column jg in an h row
    const int jpos = ((jg >> 2) & 7) * 32 + ((jg >> 5) << 2) + (jg & 3);

    // Register-resident W: k = ks*32 + m*4 .. +3
    float4 w4[8];
#pragma unroll
    for (int m = 0; m < 8; m++)
        w4[m] = *(const float4*)&w_hh[jg * Hsz + ks * 32 + m * 4];

    // h_{-1} = 0
    for (int idx = tid; idx < RMC * Hsz; idx += 1024) hbuf[0][idx] = 0.0f;

    // Peer-CTA addresses of the two h buffers
    uint32_t l0 = smem_u32(&hbuf[0][0]), l1 = smem_u32(&hbuf[1][0]);
    uint32_t p0, p1;
    asm("mapa.shared::cluster.u32 %0, %1, %2;" : "=r"(p0) : "r"(l0), "r"(rank ^ 1u));
    asm("mapa.shared::cluster.u32 %0, %1, %2;" : "=r"(p1) : "r"(l1), "r"(rank ^ 1u));

    asm volatile("barrier.cluster.arrive.aligned;" ::: "memory");
    asm volatile("barrier.cluster.wait.aligned;" ::: "memory");

    // This lane's gmem column for its publish row (b0+ks)
    float* seqcol = seq + (b0 + ks) * Tsz * Hsz + jg;

    // Prefetch pre-activation for t = 0
    float nv = seqcol[0];

    for (int t = 0; t < Tsz; t++) {
        const float* hc = hbuf[t & 1];
        float*       hn = hbuf[(t & 1) ^ 1];
        uint32_t     pn = (t & 1) ? p0 : p1;

        const float pre = nv;

        float acc[RMC];
#pragma unroll
        for (int b = 0; b < RMC; b++) acc[b] = 0.0f;

        const float4* hv = (const float4*)hc + ks;   // + b*64 + m*8
#pragma unroll
        for (int m = 0; m < 8; m++) {
            const float4 w = w4[m];
#pragma unroll
            for (int b = 0; b < RMC; b++) {
                float4 h = hv[b * 64 + m * 8];
                acc[b] = fmaf(w.x, h.x, acc[b]);
                acc[b] = fmaf(w.y, h.y, acc[b]);
                acc[b] = fmaf(w.z, h.z, acc[b]);
                acc[b] = fmaf(w.w, h.w, acc[b]);
            }
        }

        // Halving-exchange reduction over the 3 ks lane bits (7 shfls).
        // After round r, acc[0..(4>>r)-1] hold sums for b with high bits == ks's.
#pragma unroll
        for (int b = 0; b < 4; b++) {
            float send = (ks & 4) ? acc[b] : acc[b + 4];
            float recv = __shfl_xor_sync(0xffffffffu, send, 4);
            acc[b] = ((ks & 4) ? acc[b + 4] : acc[b]) + recv;
        }
#pragma unroll
        for (int b = 0; b < 2; b++) {
            float send = (ks & 2) ? acc[b] : acc[b + 2];
            float recv = __shfl_xor_sync(0xffffffffu, send, 2);
            acc[b] = ((ks & 2) ? acc[b + 2] : acc[b]) + recv;
        }
        {
            float send = (ks & 1) ? acc[0] : acc[1];
            float recv = __shfl_xor_sync(0xffffffffu, send, 1);
            acc[0] = ((ks & 1) ? acc[1] : acc[0]) + recv;
        }

        // Lane finalizes row b == ks
        const float hval = tanhf(acc[0] + pre);
        const int   spos = ks * Hsz + jpos;

        hn[spos] = hval;
        asm volatile("st.shared::cluster.f32 [%0], %1;"
                     :: "r"(pn + (uint32_t)spos * 4u), "f"(hval) : "memory");

        // Publish done -> arrive; overlap gmem store + next prefetch with wait
        asm volatile("barrier.cluster.arrive.aligned;" ::: "memory");

        seqcol[t * Hsz] = hval;
        if (t + 1 < Tsz) nv = seqcol[(t + 1) * Hsz];

        asm volatile("barrier.cluster.wait.aligned;" ::: "memory");
    }
}

// ---------------------------------------------------------------------------
// Final FC: out[b] = h[b, T-1, :] . w_fc + b_fc     (one warp per batch row)
// ---------------------------------------------------------------------------
__global__ __launch_bounds__(256) void fc_kernel(
    const float* __restrict__ seq, const float* __restrict__ wfc,
    const float* __restrict__ bfc, float* __restrict__ out)
{
    int warp = (blockIdx.x * blockDim.x + threadIdx.x) >> 5;
    int lane = threadIdx.x & 31;
    if (warp >= Bsz) return;
    const float* hrow = &seq[(warp * Tsz + (Tsz - 1)) * Hsz];
    float s = 0.0f;
#pragma unroll
    for (int i = lane; i < Hsz; i += 32) s = fmaf(hrow[i], wfc[i], s);
#pragma unroll
    for (int o = 16; o; o >>= 1) s += __shfl_xor_sync(0xffffffffu, s, o);
    if (lane == 0) out[warp] = s + bfc[0];
}

// ---------------------------------------------------------------------------
extern "C" void kernel_launch(void* const* d_in, const int* in_sizes, int n_in,
                              void* d_out, int out_size)
{
    const float* x     = (const float*)d_in[0];
    const float* w_ih0 = (const float*)d_in[1];
    const float* w_hh0 = (const float*)d_in[2];
    const float* b_ih0 = (const float*)d_in[3];
    const float* b_hh0 = (const float*)d_in[4];
    const float* w_ih1 = (const float*)d_in[5];
    const float* w_hh1 = (const float*)d_in[6];
    const float* b_ih1 = (const float*)d_in[7];
    const float* b_hh1 = (const float*)d_in[8];
    const float* w_ih2 = (const float*)d_in[9];
    const float* w_hh2 = (const float*)d_in[10];
    const float* b_ih2 = (const float*)d_in[11];
    const float* b_hh2 = (const float*)d_in[12];
    const float* w_fc  = (const float*)d_in[13];
    const float* b_fc  = (const float*)d_in[14];
    float* out = (float*)d_out;

    float *seqA, *seqB;
    cudaGetSymbolAddress((void**)&seqA, g_seqA);
    cudaGetSymbolAddress((void**)&seqB, g_seqB);

    dim3 pgrid(Bsz * Tsz / PBM, Hsz / PBN);   // (2048, 4)
    const int rec_grid = (Bsz / RMC) * 2;     // 128 CTAs = 64 clusters

    // Layer 0
    proj_kernel<<<pgrid, 256>>>(x, w_ih0, b_ih0, b_hh0, seqA, Isz);
    rec4_kernel<<<rec_grid, 1024>>>(w_hh0, seqA);

    // Layer 1
    proj_kernel<<<pgrid, 256>>>(seqA, w_ih1, b_ih1, b_hh1, seqB, Hsz);
    rec4_kernel<<<rec_grid, 1024>>>(w_hh1, seqB);

    // Layer 2
    proj_kernel<<<pgrid, 256>>>(seqB, w_ih2, b_ih2, b_hh2, seqA, Hsz);
    rec4_kernel<<<rec_grid, 1024>>>(w_hh2, seqA);

    // Head
    fc_kernel<<<(Bsz * 32 + 255) / 256, 256>>>(seqA, w_fc, b_fc, out);
}

// round 9
// speedup vs baseline: 3.7854x; 3.7854x over previous
#include <cuda_runtime.h>
#include <cuda_fp16.h>
#include <math.h>
#include <stdint.h>

#define Bsz 512
#define Tsz 512
#define Isz 64
#define Hsz 256

// Scratch: two full-sequence buffers (ping-pong between layers).
__device__ float g_seqA[Bsz * Tsz * Hsz];   // 256 MiB
__device__ float g_seqB[Bsz * Tsz * Hsz];   // 256 MiB

__device__ __forceinline__ uint32_t smem_u32(const void* p) {
    uint32_t a;
    asm("{ .reg .u64 t; cvta.to.shared.u64 t, %1; cvt.u32.u64 %0, t; }"
        : "=r"(a) : "l"(p));
    return a;
}

// ---------------------------------------------------------------------------
// Projection GEMM: C[M, Hsz] = X[M, K] @ W[Hsz, K]^T + b1 + b2
// ---------------------------------------------------------------------------
#define PBM 128
#define PBN 64
#define PBK 32
#define PTM 8
#define PTN 4

__global__ __launch_bounds__(256) void proj_kernel(
    const float* __restrict__ X, const float* __restrict__ W,
    const float* __restrict__ b1, const float* __restrict__ b2,
    float* __restrict__ C, int K)
{
    __shared__ float Xs[PBK][PBM + 4];
    __shared__ float Ws[PBK][PBN + 4];

    const int tid = threadIdx.x;
    const int tx = tid & 15;
    const int ty = tid >> 4;
    const int m0 = blockIdx.x * PBM;
    const int n0 = blockIdx.y * PBN;

    float acc[PTM][PTN];
#pragma unroll
    for (int i = 0; i < PTM; i++)
#pragma unroll
        for (int j = 0; j < PTN; j++) acc[i][j] = 0.0f;

    for (int kt = 0; kt < K; kt += PBK) {
#pragma unroll
        for (int l = 0; l < 4; l++) {
            int id  = tid + 256 * l;
            int row = id >> 3;
            int kq  = (id & 7) * 4;
            float4 v = *(const float4*)&X[(m0 + row) * K + kt + kq];
            Xs[kq + 0][row] = v.x;
            Xs[kq + 1][row] = v.y;
            Xs[kq + 2][row] = v.z;
            Xs[kq + 3][row] = v.w;
        }
#pragma unroll
        for (int l = 0; l < 2; l++) {
            int id  = tid + 256 * l;
            int row = id >> 3;
            int kq  = (id & 7) * 4;
            float4 v = *(const float4*)&W[(n0 + row) * K + kt + kq];
            Ws[kq + 0][row] = v.x;
            Ws[kq + 1][row] = v.y;
            Ws[kq + 2][row] = v.z;
            Ws[kq + 3][row] = v.w;
        }
        __syncthreads();

#pragma unroll
        for (int k = 0; k < PBK; k++) {
            float a[PTM], w[PTN];
#pragma unroll
            for (int i = 0; i < PTM; i++) a[i] = Xs[k][ty * PTM + i];
#pragma unroll
            for (int j = 0; j < PTN; j++) w[j] = Ws[k][tx * PTN + j];
#pragma unroll
            for (int i = 0; i < PTM; i++)
#pragma unroll
                for (int j = 0; j < PTN; j++)
                    acc[i][j] = fmaf(a[i], w[j], acc[i][j]);
        }
        __syncthreads();
    }

#pragma unroll
    for (int j = 0; j < PTN; j++) {
        int n = n0 + tx * PTN + j;
        float bb = b1[n] + b2[n];
#pragma unroll
        for (int i = 0; i < PTM; i++) {
            C[(m0 + ty * PTM + i) * Hsz + n] = acc[i][j] + bb;
        }
    }
}

// ---------------------------------------------------------------------------
// rec6: HMMA (mma.sync) recurrence, single CTA per 8 batch rows, no cluster.
// 64 CTAs x 256 threads (8 warps). Warp w owns j-rows [32w, 32w+32) as two
// m16 tiles. Per step: D[256j, 8b] = Whi*hhi + Whi*hlo + Wlo*hhi via
// mma.sync.m16n8k16 (fp16 in, fp32 accum); h = tanh(D + pre).
//   Whi: stationary A-fragments in registers (128 regs/thread).
//   Wlo: smem, pitch 528B (bank-shift 4/row), read via ldmatrix.x4.
//   h:   fp16 hi/lo ping-pong smem buffers [b][k], pitch 528B.
//   pre: cp.async double buffer [b][j], pitch 1040B.
// Two __syncthreads per step; no DSMEM, no cluster barrier.
// ---------------------------------------------------------------------------
#define BC 8                         // batch rows per CTA
#define SZ_WLO   (256 * 528)         // 135168
#define OFF_HB   SZ_WLO              // hB: [buf][hi 4224 | lo 4224] = 8448/buf
#define OFF_PRE  (OFF_HB + 2 * 8448) // preS: [buf][8][1040B] = 8320/buf
#define SM_REC   (OFF_PRE + 2 * 8320)

__device__ __forceinline__ uint32_t lds_u32(uint32_t a) {
    uint32_t v; asm volatile("ld.shared.b32 %0, [%1];" : "=r"(v) : "r"(a)); return v;
}
__device__ __forceinline__ float lds_f32(uint32_t a) {
    float v; asm volatile("ld.shared.f32 %0, [%1];" : "=f"(v) : "r"(a)); return v;
}
__device__ __forceinline__ void sts_u32(uint32_t a, uint32_t v) {
    asm volatile("st.shared.b32 [%0], %1;" :: "r"(a), "r"(v) : "memory");
}
__device__ __forceinline__ void sts_u16(uint32_t a, uint32_t v) {
    asm volatile("st.shared.u16 [%0], %1;" :: "r"(a), "r"(v) : "memory");
}
__device__ __forceinline__ void cp16(uint32_t dst, const void* src) {
    asm volatile("cp.async.cg.shared.global [%0], [%1], 16;"
                 :: "r"(dst), "l"(src) : "memory");
}
__device__ __forceinline__ void ldsm4(uint32_t* r, uint32_t a) {
    asm volatile("ldmatrix.sync.aligned.m8n8.x4.shared.b16 {%0,%1,%2,%3}, [%4];"
                 : "=r"(r[0]), "=r"(r[1]), "=r"(r[2]), "=r"(r[3]) : "r"(a));
}
__device__ __forceinline__ void mma16816(float* c,
    uint32_t a0, uint32_t a1, uint32_t a2, uint32_t a3, uint32_t b0, uint32_t b1)
{
    asm volatile(
        "mma.sync.aligned.m16n8k16.row.col.f32.f16.f16.f32 "
        "{%0,%1,%2,%3}, {%4,%5,%6,%7}, {%8,%9}, {%0,%1,%2,%3};"
        : "+f"(c[0]), "+f"(c[1]), "+f"(c[2]), "+f"(c[3])
        : "r"(a0), "r"(a1), "r"(a2), "r"(a3), "r"(b0), "r"(b1));
}

__global__ void __launch_bounds__(256, 1)
rec6_kernel(const float* __restrict__ w_hh, float* __restrict__ seq)
{
    extern __shared__ char smx[];
    const uint32_t u_base = smem_u32(smx);
    const uint32_t u_wlo  = u_base;
    const uint32_t u_hb   = u_base + OFF_HB;
    const uint32_t u_pre  = u_base + OFF_PRE;

    const int tid  = threadIdx.x;
    const int lane = tid & 31;
    const int w    = tid >> 5;
    const int jb   = w * 32;
    const int b0   = blockIdx.x * BC;

    // ---- Whi fragments (registers) + Wlo hi-residual into smem ----
    uint32_t whi[2][16][4];
    {
        const int mr = lane >> 2;          // fragment row within tile
        const int kc = (lane & 3) * 2;     // fragment col pair base
#pragma unroll
        for (int tt = 0; tt < 2; tt++) {
#pragma unroll
            for (int ks = 0; ks < 16; ks++) {
#pragma unroll
                for (int q = 0; q < 4; q++) {
                    int m = jb + tt * 16 + mr + (q & 1) * 8;
                    int k = ks * 16 + kc + (q >> 1) * 8;
                    float2 v = *(const float2*)&w_hh[m * Hsz + k];
                    __half h0 = __float2half_rn(v.x);
                    __half h1 = __float2half_rn(v.y);
                    __half l0 = __float2half_rn(v.x - __half2float(h0));
                    __half l1 = __float2half_rn(v.y - __half2float(h1));
                    whi[tt][ks][q] = (uint32_t)__half_as_ushort(h0)
                                   | ((uint32_t)__half_as_ushort(h1) << 16);
                    sts_u32(u_wlo + (uint32_t)(m * 528 + k * 2),
                            (uint32_t)__half_as_ushort(l0)
                          | ((uint32_t)__half_as_ushort(l1) << 16));
                }
            }
        }
    }

    // Zero h buffer 0 (hi + lo)
    for (int i = tid; i < 8448 / 4; i += 256) sts_u32(u_hb + i * 4, 0u);

    // Initial pre load (t = 0) into pre buf 0
    {
        int b = tid >> 5, c = tid & 31;
        const float* src = seq + (size_t)(b0 + b) * Tsz * Hsz;
        uint32_t dst = u_pre + (uint32_t)(b * 1040);
        cp16(dst + c * 16, src + c * 4);
        cp16(dst + (c + 32) * 16, src + (c + 32) * 4);
        asm volatile("cp.async.commit_group;" ::: "memory");
        asm volatile("cp.async.wait_group 0;" ::: "memory");
    }
    __syncthreads();

    // Per-lane constant addresses
    const uint32_t wlo_lane = u_wlo
        + (uint32_t)((jb + (lane & 7) + ((lane >> 3) & 1) * 8) * 528)
        + (uint32_t)(((lane >> 4) & 1) * 16);
    const uint32_t b_off = (uint32_t)((lane >> 2) * 528 + (lane & 3) * 4);

    for (int t = 0; t < Tsz; t++) {
        const int cur = t & 1, nxt = cur ^ 1;
        const uint32_t hbc_hi = u_hb + (uint32_t)(cur * 8448);
        const uint32_t hbc_lo = hbc_hi + 4224u;
        const uint32_t hbn_hi = u_hb + (uint32_t)(nxt * 8448);
        const uint32_t hbn_lo = hbn_hi + 4224u;

        // Prefetch pre for t+1 (clamped; overlapped with MMA chain)
        {
            int tn = (t + 1 < Tsz) ? t + 1 : t;
            int b = tid >> 5, c = tid & 31;
            const float* src = seq + ((size_t)(b0 + b) * Tsz + tn) * Hsz;
            uint32_t dst = u_pre + (uint32_t)(nxt * 8320 + b * 1040);
            cp16(dst + c * 16, src + c * 4);
            cp16(dst + (c + 32) * 16, src + (c + 32) * 4);
            asm volatile("cp.async.commit_group;" ::: "memory");
        }

        float cacc[2][4];
#pragma unroll
        for (int tt = 0; tt < 2; tt++)
#pragma unroll
            for (int i = 0; i < 4; i++) cacc[tt][i] = 0.0f;

#pragma unroll
        for (int ks = 0; ks < 16; ks++) {
            uint32_t bh0 = lds_u32(hbc_hi + b_off + ks * 32);
            uint32_t bh1 = lds_u32(hbc_hi + b_off + ks * 32 + 16);
            uint32_t bl0 = lds_u32(hbc_lo + b_off + ks * 32);
            uint32_t bl1 = lds_u32(hbc_lo + b_off + ks * 32 + 16);
#pragma unroll
            for (int tt = 0; tt < 2; tt++) {
                uint32_t wl[4];
                ldsm4(wl, wlo_lane + (uint32_t)(tt * 16 * 528 + ks * 32));
                mma16816(cacc[tt], whi[tt][ks][0], whi[tt][ks][1],
                         whi[tt][ks][2], whi[tt][ks][3], bh0, bh1);
                mma16816(cacc[tt], whi[tt][ks][0], whi[tt][ks][1],
                         whi[tt][ks][2], whi[tt][ks][3], bl0, bl1);
                mma16816(cacc[tt], wl[0], wl[1], wl[2], wl[3], bh0, bh1);
            }
        }

        // My prefetch (t+1) may still be in flight; my (t)'s group is done:
        asm volatile("cp.async.wait_group 1;" ::: "memory");
        __syncthreads();   // all threads' pre[cur] complete & visible

        const uint32_t prec = u_pre + (uint32_t)(cur * 8320);
        const int cb = (lane & 3) * 2;
#pragma unroll
        for (int tt = 0; tt < 2; tt++) {
#pragma unroll
            for (int half = 0; half < 2; half++) {
                int j = jb + tt * 16 + (lane >> 2) + half * 8;
                float p0 = lds_f32(prec + (uint32_t)(cb * 1040 + j * 4));
                float p1 = lds_f32(prec + (uint32_t)((cb + 1) * 1040 + j * 4));
                float h0 = tanhf(cacc[tt][half * 2 + 0] + p0);
                float h1 = tanhf(cacc[tt][half * 2 + 1] + p1);

                __half h0h = __float2half_rn(h0);
                __half h0l = __float2half_rn(h0 - __half2float(h0h));
                __half h1h = __float2half_rn(h1);
                __half h1l = __float2half_rn(h1 - __half2float(h1h));
                sts_u16(hbn_hi + (uint32_t)(cb * 528 + j * 2),
                        (uint32_t)__half_as_ushort(h0h));
                sts_u16(hbn_lo + (uint32_t)(cb * 528 + j * 2),
                        (uint32_t)__half_as_ushort(h0l));
                sts_u16(hbn_hi + (uint32_t)((cb + 1) * 528 + j * 2),
                        (uint32_t)__half_as_ushort(h1h));
                sts_u16(hbn_lo + (uint32_t)((cb + 1) * 528 + j * 2),
                        (uint32_t)__half_as_ushort(h1l));

                seq[((size_t)(b0 + cb) * Tsz + t) * Hsz + j]     = h0;
                seq[((size_t)(b0 + cb + 1) * Tsz + t) * Hsz + j] = h1;
            }
        }

        __syncthreads();   // h[nxt] visible before next step's MMA reads
    }
}

// ---------------------------------------------------------------------------
// Final FC: out[b] = h[b, T-1, :] . w_fc + b_fc     (one warp per batch row)
// ---------------------------------------------------------------------------
__global__ __launch_bounds__(256) void fc_kernel(
    const float* __restrict__ seq, const float* __restrict__ wfc,
    const float* __restrict__ bfc, float* __restrict__ out)
{
    int warp = (blockIdx.x * blockDim.x + threadIdx.x) >> 5;
    int lane = threadIdx.x & 31;
    if (warp >= Bsz) return;
    const float* hrow = &seq[(warp * Tsz + (Tsz - 1)) * Hsz];
    float s = 0.0f;
#pragma unroll
    for (int i = lane; i < Hsz; i += 32) s = fmaf(hrow[i], wfc[i], s);
#pragma unroll
    for (int o = 16; o; o >>= 1) s += __shfl_xor_sync(0xffffffffu, s, o);
    if (lane == 0) out[warp] = s + bfc[0];
}

// ---------------------------------------------------------------------------
extern "C" void kernel_launch(void* const* d_in, const int* in_sizes, int n_in,
                              void* d_out, int out_size)
{
    const float* x     = (const float*)d_in[0];
    const float* w_ih0 = (const float*)d_in[1];
    const float* w_hh0 = (const float*)d_in[2];
    const float* b_ih0 = (const float*)d_in[3];
    const float* b_hh0 = (const float*)d_in[4];
    const float* w_ih1 = (const float*)d_in[5];
    const float* w_hh1 = (const float*)d_in[6];
    const float* b_ih1 = (const float*)d_in[7];
    const float* b_hh1 = (const float*)d_in[8];
    const float* w_ih2 = (const float*)d_in[9];
    const float* w_hh2 = (const float*)d_in[10];
    const float* b_ih2 = (const float*)d_in[11];
    const float* b_hh2 = (const float*)d_in[12];
    const float* w_fc  = (const float*)d_in[13];
    const float* b_fc  = (const float*)d_in[14];
    float* out = (float*)d_out;

    float *seqA, *seqB;
    cudaGetSymbolAddress((void**)&seqA, g_seqA);
    cudaGetSymbolAddress((void**)&seqB, g_seqB);

    cudaFuncSetAttribute(rec6_kernel,
                         cudaFuncAttributeMaxDynamicSharedMemorySize, SM_REC);

    dim3 pgrid(Bsz * Tsz / PBM, Hsz / PBN);   // (2048, 4)
    const int rec_grid = Bsz / BC;            // 64 CTAs

    // Layer 0
    proj_kernel<<<pgrid, 256>>>(x, w_ih0, b_ih0, b_hh0, seqA, Isz);
    rec6_kernel<<<rec_grid, 256, SM_REC>>>(w_hh0, seqA);

    // Layer 1
    proj_kernel<<<pgrid, 256>>>(seqA, w_ih1, b_ih1, b_hh1, seqB, Hsz);
    rec6_kernel<<<rec_grid, 256, SM_REC>>>(w_hh1, seqB);

    // Layer 2
    proj_kernel<<<pgrid, 256>>>(seqB, w_ih2, b_ih2, b_hh2, seqA, Hsz);
    rec6_kernel<<<rec_grid, 256, SM_REC>>>(w_hh2, seqA);

    // Head
    fc_kernel<<<(Bsz * 32 + 255) / 256, 256>>>(seqA, w_fc, b_fc, out);
}

// round 10
// speedup vs baseline: 4.3601x; 1.1518x over previous
#include <cuda_runtime.h>
#include <cuda_fp16.h>
#include <math.h>
#include <stdint.h>

#define Bsz 512
#define Tsz 512
#define Isz 64
#define Hsz 256

// Scratch buffers.
__device__ float  g_seq[Bsz * Tsz * Hsz];    // fp32 pre-activations (per layer)
__device__ __half g_hhi[Bsz * Tsz * Hsz];    // h hi fp16 plane
__device__ __half g_hlo[Bsz * Tsz * Hsz];    // h lo fp16 plane
__device__ __half g_xhi[Bsz * Tsz * Isz];    // x hi fp16 plane
__device__ __half g_xlo[Bsz * Tsz * Isz];    // x lo fp16 plane

__device__ __forceinline__ uint32_t smem_u32(const void* p) {
    uint32_t a;
    asm("{ .reg .u64 t; cvta.to.shared.u64 t, %1; cvt.u32.u64 %0, t; }"
        : "=r"(a) : "l"(p));
    return a;
}
__device__ __forceinline__ uint32_t lds_u32(uint32_t a) {
    uint32_t v; asm volatile("ld.shared.b32 %0, [%1];" : "=r"(v) : "r"(a)); return v;
}
__device__ __forceinline__ float lds_f32(uint32_t a) {
    float v; asm volatile("ld.shared.f32 %0, [%1];" : "=f"(v) : "r"(a)); return v;
}
__device__ __forceinline__ void sts_u32(uint32_t a, uint32_t v) {
    asm volatile("st.shared.b32 [%0], %1;" :: "r"(a), "r"(v) : "memory");
}
__device__ __forceinline__ void sts_u16(uint32_t a, uint32_t v) {
    asm volatile("st.shared.u16 [%0], %1;" :: "r"(a), "r"(v) : "memory");
}
__device__ __forceinline__ void cp16(uint32_t dst, const void* src) {
    asm volatile("cp.async.cg.shared.global [%0], [%1], 16;"
                 :: "r"(dst), "l"(src) : "memory");
}
__device__ __forceinline__ void ldsm4(uint32_t* r, uint32_t a) {
    asm volatile("ldmatrix.sync.aligned.m8n8.x4.shared.b16 {%0,%1,%2,%3}, [%4];"
                 : "=r"(r[0]), "=r"(r[1]), "=r"(r[2]), "=r"(r[3]) : "r"(a));
}
__device__ __forceinline__ void mma16816(float* c,
    uint32_t a0, uint32_t a1, uint32_t a2, uint32_t a3, uint32_t b0, uint32_t b1)
{
    asm volatile(
        "mma.sync.aligned.m16n8k16.row.col.f32.f16.f16.f32 "
        "{%0,%1,%2,%3}, {%4,%5,%6,%7}, {%8,%9}, {%0,%1,%2,%3};"
        : "+f"(c[0]), "+f"(c[1]), "+f"(c[2]), "+f"(c[3])
        : "r"(a0), "r"(a1), "r"(a2), "r"(a3), "r"(b0), "r"(b1));
}

// ---------------------------------------------------------------------------
// Convert x (fp32) -> hi/lo fp16 planes. 4 elements per thread.
// ---------------------------------------------------------------------------
__global__ __launch_bounds__(256) void cvt_kernel(
    const float4* __restrict__ x, __half2* __restrict__ hi, __half2* __restrict__ lo)
{
    int i = blockIdx.x * 256 + threadIdx.x;
    float4 v = x[i];
    __half h0 = __float2half_rn(v.x), h1 = __float2half_rn(v.y);
    __half h2 = __float2half_rn(v.z), h3 = __float2half_rn(v.w);
    hi[2 * i]     = __halves2half2(h0, h1);
    hi[2 * i + 1] = __halves2half2(h2, h3);
    lo[2 * i]     = __halves2half2(__float2half_rn(v.x - __half2float(h0)),
                                   __float2half_rn(v.y - __half2float(h1)));
    lo[2 * i + 1] = __halves2half2(__float2half_rn(v.z - __half2float(h2)),
                                   __float2half_rn(v.w - __half2float(h3)));
}

// ---------------------------------------------------------------------------
// proj2: HMMA projection. C[M,256] = A[M,K] @ W[256,K]^T + b1 + b2.
// A given as fp16 hi/lo planes; 3-term split: Ahi*Whi + Ahi*Wlo + Alo*Whi,
// fp32 accumulators. CTA = 128m x 64n, 8 warps (4m x 2n), warp = 32m x 32n.
// W (64 rows x K) converted to hi/lo fp16 smem once; X streamed 16-k steps
// via cp.async double buffer (48B row pitch -> 16B-aligned destinations).
// ---------------------------------------------------------------------------
#define XPL 6144   // one X plane: 128 rows * 48B

__global__ __launch_bounds__(256) void proj2_kernel(
    const __half* __restrict__ Ahi, const __half* __restrict__ Alo,
    const float* __restrict__ W, const float* __restrict__ b1,
    const float* __restrict__ b2, float* __restrict__ C, int K, int kshift)
{
    extern __shared__ char sm[];
    const int      WP    = K * 2 + 16;
    const uint32_t ub    = smem_u32(sm);
    const uint32_t u_whi = ub;
    const uint32_t u_wlo = ub + (uint32_t)(64 * WP);
    const uint32_t u_x   = ub + (uint32_t)(128 * WP);

    const int tid = threadIdx.x, lane = tid & 31, w = tid >> 5;
    const int wm = w >> 1, wn = w & 1;
    const int m0 = blockIdx.x * 128, n0 = blockIdx.y * 64;

    // W -> smem hi/lo (once; K fully resident)
    for (int idx = tid; idx < 64 * K; idx += 256) {
        int r = idx >> kshift, k = idx & (K - 1);
        float v = W[(size_t)(n0 + r) * K + k];
        __half h = __float2half_rn(v);
        __half l = __float2half_rn(v - __half2float(h));
        sts_u16(u_whi + (uint32_t)(r * WP + k * 2), (uint32_t)__half_as_ushort(h));
        sts_u16(u_wlo + (uint32_t)(r * WP + k * 2), (uint32_t)__half_as_ushort(l));
    }

    const int nk   = K >> 4;
    const int xrow = tid >> 1, xh = tid & 1;
    const uint32_t xdst = (uint32_t)(xrow * 48 + xh * 16);

    // Prologue: load kstep 0 into buffer 0
    cp16(u_x + xdst, Ahi + (size_t)(m0 + xrow) * K + xh * 8);
    cp16(u_x + XPL + xdst, Alo + (size_t)(m0 + xrow) * K + xh * 8);
    asm volatile("cp.async.commit_group;" ::: "memory");

    float acc[2][4][4];
#pragma unroll
    for (int tt = 0; tt < 2; tt++)
#pragma unroll
        for (int nb = 0; nb < 4; nb++)
#pragma unroll
            for (int i = 0; i < 4; i++) acc[tt][nb][i] = 0.0f;

    for (int kt = 0; kt < nk; kt++) {
        const int buf = kt & 1;
        if (kt + 1 < nk) {
            const uint32_t xb = u_x + (uint32_t)((buf ^ 1) * 2) * XPL;
            cp16(xb + xdst, Ahi + (size_t)(m0 + xrow) * K + (kt + 1) * 16 + xh * 8);
            cp16(xb + XPL + xdst, Alo + (size_t)(m0 + xrow) * K + (kt + 1) * 16 + xh * 8);
            asm volatile("cp.async.commit_group;" ::: "memory");
            asm volatile("cp.async.wait_group 1;" ::: "memory");
        } else {
            asm volatile("cp.async.wait_group 0;" ::: "memory");
        }
        __syncthreads();

        const uint32_t xb_hi = u_x + (uint32_t)(buf * 2) * XPL;
        const uint32_t xb_lo = xb_hi + XPL;
        const uint32_t arow  = (uint32_t)((wm * 32 + (lane & 15)) * 48 + (lane >> 4) * 16);

        uint32_t ahi[2][4], alo[2][4];
        ldsm4(ahi[0], xb_hi + arow);
        ldsm4(ahi[1], xb_hi + arow + 16 * 48);
        ldsm4(alo[0], xb_lo + arow);
        ldsm4(alo[1], xb_lo + arow + 16 * 48);

        const uint32_t bbase = (uint32_t)((wn * 32 + (lane >> 2)) * WP
                                          + kt * 32 + (lane & 3) * 4);
#pragma unroll
        for (int nb = 0; nb < 4; nb++) {
            uint32_t o  = bbase + (uint32_t)(nb * 8 * WP);
            uint32_t bh0 = lds_u32(u_whi + o), bh1 = lds_u32(u_whi + o + 16);
            uint32_t bl0 = lds_u32(u_wlo + o), bl1 = lds_u32(u_wlo + o + 16);
#pragma unroll
            for (int tt = 0; tt < 2; tt++) {
                mma16816(acc[tt][nb], ahi[tt][0], ahi[tt][1], ahi[tt][2], ahi[tt][3], bh0, bh1);
                mma16816(acc[tt][nb], ahi[tt][0], ahi[tt][1], ahi[tt][2], ahi[tt][3], bl0, bl1);
                mma16816(acc[tt][nb], alo[tt][0], alo[tt][1], alo[tt][2], alo[tt][3], bh0, bh1);
            }
        }
        __syncthreads();
    }

    // Epilogue: bias + fp32 store
#pragma unroll
    for (int tt = 0; tt < 2; tt++) {
#pragma unroll
        for (int nb = 0; nb < 4; nb++) {
            int n  = n0 + wn * 32 + nb * 8 + (lane & 3) * 2;
            float bb0 = b1[n] + b2[n];
            float bb1 = b1[n + 1] + b2[n + 1];
            int m = m0 + wm * 32 + tt * 16 + (lane >> 2);
            float2 v0 = {acc[tt][nb][0] + bb0, acc[tt][nb][1] + bb1};
            float2 v1 = {acc[tt][nb][2] + bb0, acc[tt][nb][3] + bb1};
            *(float2*)&C[(size_t)m * Hsz + n]       = v0;
            *(float2*)&C[(size_t)(m + 8) * Hsz + n] = v1;
        }
    }
}

// ---------------------------------------------------------------------------
// rec7: HMMA recurrence (rec6 structure), now emitting h as fp16 hi/lo
// planes (no fp32 h store). pre still read from fp32 seq (proj2 output).
// ---------------------------------------------------------------------------
#define BC 8
#define SZ_WLO   (256 * 528)
#define OFF_HB   SZ_WLO
#define OFF_PRE  (OFF_HB + 2 * 8448)
#define SM_REC   (OFF_PRE + 2 * 8320)

__global__ void __launch_bounds__(256, 1)
rec7_kernel(const float* __restrict__ w_hh, const float* __restrict__ seq,
            __half* __restrict__ hh, __half* __restrict__ hl)
{
    extern __shared__ char smx[];
    const uint32_t u_base = smem_u32(smx);
    const uint32_t u_wlo  = u_base;
    const uint32_t u_hb   = u_base + OFF_HB;
    const uint32_t u_pre  = u_base + OFF_PRE;

    const int tid  = threadIdx.x;
    const int lane = tid & 31;
    const int w    = tid >> 5;
    const int jb   = w * 32;
    const int b0   = blockIdx.x * BC;

    uint32_t whi[2][16][4];
    {
        const int mr = lane >> 2;
        const int kc = (lane & 3) * 2;
#pragma unroll
        for (int tt = 0; tt < 2; tt++) {
#pragma unroll
            for (int ks = 0; ks < 16; ks++) {
#pragma unroll
                for (int q = 0; q < 4; q++) {
                    int m = jb + tt * 16 + mr + (q & 1) * 8;
                    int k = ks * 16 + kc + (q >> 1) * 8;
                    float2 v = *(const float2*)&w_hh[m * Hsz + k];
                    __half h0 = __float2half_rn(v.x);
                    __half h1 = __float2half_rn(v.y);
                    __half l0 = __float2half_rn(v.x - __half2float(h0));
                    __half l1 = __float2half_rn(v.y - __half2float(h1));
                    whi[tt][ks][q] = (uint32_t)__half_as_ushort(h0)
                                   | ((uint32_t)__half_as_ushort(h1) << 16);
                    sts_u32(u_wlo + (uint32_t)(m * 528 + k * 2),
                            (uint32_t)__half_as_ushort(l0)
                          | ((uint32_t)__half_as_ushort(l1) << 16));
                }
            }
        }
    }

    for (int i = tid; i < 8448 / 4; i += 256) sts_u32(u_hb + i * 4, 0u);

    {
        int b = tid >> 5, c = tid & 31;
        const float* src = seq + (size_t)(b0 + b) * Tsz * Hsz;
        uint32_t dst = u_pre + (uint32_t)(b * 1040);
        cp16(dst + c * 16, src + c * 4);
        cp16(dst + (c + 32) * 16, src + (c + 32) * 4);
        asm volatile("cp.async.commit_group;" ::: "memory");
        asm volatile("cp.async.wait_group 0;" ::: "memory");
    }
    __syncthreads();

    const uint32_t wlo_lane = u_wlo
        + (uint32_t)((jb + (lane & 7) + ((lane >> 3) & 1) * 8) * 528)
        + (uint32_t)(((lane >> 4) & 1) * 16);
    const uint32_t b_off = (uint32_t)((lane >> 2) * 528 + (lane & 3) * 4);

    for (int t = 0; t < Tsz; t++) {
        const int cur = t & 1, nxt = cur ^ 1;
        const uint32_t hbc_hi = u_hb + (uint32_t)(cur * 8448);
        const uint32_t hbc_lo = hbc_hi + 4224u;
        const uint32_t hbn_hi = u_hb + (uint32_t)(nxt * 8448);
        const uint32_t hbn_lo = hbn_hi + 4224u;

        {
            int tn = (t + 1 < Tsz) ? t + 1 : t;
            int b = tid >> 5, c = tid & 31;
            const float* src = seq + ((size_t)(b0 + b) * Tsz + tn) * Hsz;
            uint32_t dst = u_pre + (uint32_t)(nxt * 8320 + b * 1040);
            cp16(dst + c * 16, src + c * 4);
            cp16(dst + (c + 32) * 16, src + (c + 32) * 4);
            asm volatile("cp.async.commit_group;" ::: "memory");
        }

        float cacc[2][4];
#pragma unroll
        for (int tt = 0; tt < 2; tt++)
#pragma unroll
            for (int i = 0; i < 4; i++) cacc[tt][i] = 0.0f;

#pragma unroll
        for (int ks = 0; ks < 16; ks++) {
            uint32_t bh0 = lds_u32(hbc_hi + b_off + ks * 32);
            uint32_t bh1 = lds_u32(hbc_hi + b_off + ks * 32 + 16);
            uint32_t bl0 = lds_u32(hbc_lo + b_off + ks * 32);
            uint32_t bl1 = lds_u32(hbc_lo + b_off + ks * 32 + 16);
#pragma unroll
            for (int tt = 0; tt < 2; tt++) {
                uint32_t wl[4];
                ldsm4(wl, wlo_lane + (uint32_t)(tt * 16 * 528 + ks * 32));
                mma16816(cacc[tt], whi[tt][ks][0], whi[tt][ks][1],
                         whi[tt][ks][2], whi[tt][ks][3], bh0, bh1);
                mma16816(cacc[tt], whi[tt][ks][0], whi[tt][ks][1],
                         whi[tt][ks][2], whi[tt][ks][3], bl0, bl1);
                mma16816(cacc[tt], wl[0], wl[1], wl[2], wl[3], bh0, bh1);
            }
        }

        asm volatile("cp.async.wait_group 1;" ::: "memory");
        __syncthreads();

        const uint32_t prec = u_pre + (uint32_t)(cur * 8320);
        const int cb = (lane & 3) * 2;
#pragma unroll
        for (int tt = 0; tt < 2; tt++) {
#pragma unroll
            for (int half = 0; half < 2; half++) {
                int j = jb + tt * 16 + (lane >> 2) + half * 8;
                float p0 = lds_f32(prec + (uint32_t)(cb * 1040 + j * 4));
                float p1 = lds_f32(prec + (uint32_t)((cb + 1) * 1040 + j * 4));
                float h0 = tanhf(cacc[tt][half * 2 + 0] + p0);
                float h1 = tanhf(cacc[tt][half * 2 + 1] + p1);

                __half h0h = __float2half_rn(h0);
                __half h0l = __float2half_rn(h0 - __half2float(h0h));
                __half h1h = __float2half_rn(h1);
                __half h1l = __float2half_rn(h1 - __half2float(h1h));
                sts_u16(hbn_hi + (uint32_t)(cb * 528 + j * 2),
                        (uint32_t)__half_as_ushort(h0h));
                sts_u16(hbn_lo + (uint32_t)(cb * 528 + j * 2),
                        (uint32_t)__half_as_ushort(h0l));
                sts_u16(hbn_hi + (uint32_t)((cb + 1) * 528 + j * 2),
                        (uint32_t)__half_as_ushort(h1h));
                sts_u16(hbn_lo + (uint32_t)((cb + 1) * 528 + j * 2),
                        (uint32_t)__half_as_ushort(h1l));

                size_t g0 = ((size_t)(b0 + cb) * Tsz + t) * Hsz + j;
                size_t g1 = ((size_t)(b0 + cb + 1) * Tsz + t) * Hsz + j;
                hh[g0] = h0h; hl[g0] = h0l;
                hh[g1] = h1h; hl[g1] = h1l;
            }
        }

        __syncthreads();
    }
}

// ---------------------------------------------------------------------------
// fc2: out[b] = (hi+lo)[b, T-1, :] . w_fc + b_fc   (one warp per batch row)
// ---------------------------------------------------------------------------
__global__ __launch_bounds__(256) void fc2_kernel(
    const __half* __restrict__ hh, const __half* __restrict__ hl,
    const float* __restrict__ wfc, const float* __restrict__ bfc,
    float* __restrict__ out)
{
    int warp = (blockIdx.x * blockDim.x + threadIdx.x) >> 5;
    int lane = threadIdx.x & 31;
    if (warp >= Bsz) return;
    size_t base = ((size_t)warp * Tsz + (Tsz - 1)) * Hsz;
    float s = 0.0f;
#pragma unroll
    for (int i = lane; i < Hsz; i += 32) {
        float h = __half2float(hh[base + i]) + __half2float(hl[base + i]);
        s = fmaf(h, wfc[i], s);
    }
#pragma unroll
    for (int o = 16; o; o >>= 1) s += __shfl_xor_sync(0xffffffffu, s, o);
    if (lane == 0) out[warp] = s + bfc[0];
}

// ---------------------------------------------------------------------------
extern "C" void kernel_launch(void* const* d_in, const int* in_sizes, int n_in,
                              void* d_out, int out_size)
{
    const float* x     = (const float*)d_in[0];
    const float* w_ih0 = (const float*)d_in[1];
    const float* w_hh0 = (const float*)d_in[2];
    const float* b_ih0 = (const float*)d_in[3];
    const float* b_hh0 = (const float*)d_in[4];
    const float* w_ih1 = (const float*)d_in[5];
    const float* w_hh1 = (const float*)d_in[6];
    const float* b_ih1 = (const float*)d_in[7];
    const float* b_hh1 = (const float*)d_in[8];
    const float* w_ih2 = (const float*)d_in[9];
    const float* w_hh2 = (const float*)d_in[10];
    const float* b_ih2 = (const float*)d_in[11];
    const float* b_hh2 = (const float*)d_in[12];
    const float* w_fc  = (const float*)d_in[13];
    const float* b_fc  = (const float*)d_in[14];
    float* out = (float*)d_out;

    float *seq; __half *hhi, *hlo, *xhi, *xlo;
    cudaGetSymbolAddress((void**)&seq, g_seq);
    cudaGetSymbolAddress((void**)&hhi, g_hhi);
    cudaGetSymbolAddress((void**)&hlo, g_hlo);
    cudaGetSymbolAddress((void**)&xhi, g_xhi);
    cudaGetSymbolAddress((void**)&xlo, g_xlo);

    const int psm256 = 128 * (256 * 2 + 16) + 4 * XPL;   // 92160
    const int psm64  = 128 * (64 * 2 + 16) + 4 * XPL;    // 43008

    cudaFuncSetAttribute(proj2_kernel,
                         cudaFuncAttributeMaxDynamicSharedMemorySize, psm256);
    cudaFuncSetAttribute(rec7_kernel,
                         cudaFuncAttributeMaxDynamicSharedMemorySize, SM_REC);

    dim3 pgrid(Bsz * Tsz / 128, Hsz / 64);   // (2048, 4)

    // x -> fp16 hi/lo planes
    cvt_kernel<<<(Bsz * Tsz * Isz / 4) / 256, 256>>>(
        (const float4*)x, (__half2*)xhi, (__half2*)xlo);

    // Layer 0
    proj2_kernel<<<pgrid, 256, psm64>>>(xhi, xlo, w_ih0, b_ih0, b_hh0, seq, Isz, 6);
    rec7_kernel<<<Bsz / BC, 256, SM_REC>>>(w_hh0, seq, hhi, hlo);

    // Layer 1
    proj2_kernel<<<pgrid, 256, psm256>>>(hhi, hlo, w_ih1, b_ih1, b_hh1, seq, Hsz, 8);
    rec7_kernel<<<Bsz / BC, 256, SM_REC>>>(w_hh1, seq, hhi, hlo);

    // Layer 2
    proj2_kernel<<<pgrid, 256, psm256>>>(hhi, hlo, w_ih2, b_ih2, b_hh2, seq, Hsz, 8);
    rec7_kernel<<<Bsz / BC, 256, SM_REC>>>(w_hh2, seq, hhi, hlo);

    // Head
    fc2_kernel<<<(Bsz * 32) / 256, 256>>>(hhi, hlo, w_fc, b_fc, out);
}